// round 7
// baseline (speedup 1.0000x reference)
#include <cuda_runtime.h>
#include <cuda_bf16.h>

// loss = sum_{b,c,s,h,w} (out[b,c,2s,h,w] - target[b,c,2s+1,h,w])^2 / (C*H*Wd * W/2)
// B=8, C=32, W=16 (s=0..7), H=128, Wd=128.
//
// 2048 slabs (g = flattened b,c,s). Slab g:
//   out float4 base : out4 + (g<<13)          (4096 float4 = 64 KB)
//   tgt float4 base : tgt4 + (g<<13) + 4096   (4096 float4 = 64 KB)
//
// 512 CTAs x 4 contiguous slabs each (single resident wave, 4x fewer tails).
// Inner loop identical to the proven roofline loop. Fire-and-forget REDG tail;
// one spinner thread finalizes and re-arms globals for graph replay.

#define NBLOCKS 512
#define SLABS_PER_CTA 4
#define NTHREADS 256
#define PER_THREAD 16          // 4096 / 256
#define SLAB_STRIDE4 8192      // float4 per slab pair region (1<<13)

__device__ float        g_accum = 0.0f;  // re-armed by spinner each launch
__device__ unsigned int g_count = 0;     // re-armed by spinner each launch

__global__ __launch_bounds__(NTHREADS) void cont_loss_fused_kernel(
    const float4* __restrict__ out4, const float4* __restrict__ tgt4,
    float* __restrict__ result)
{
    // CTA b handles slabs 4b .. 4b+3 (contiguous 256 KB per tensor side)
    const long long base = ((long long)blockIdx.x * SLABS_PER_CTA) << 13;
    const float4* __restrict__ op = out4 + base + threadIdx.x;
    const float4* __restrict__ tp = tgt4 + base + 4096 + threadIdx.x;

    float a0 = 0.0f, a1 = 0.0f, a2 = 0.0f, a3 = 0.0f;
    #pragma unroll
    for (int j = 0; j < SLABS_PER_CTA; j++) {
        #pragma unroll
        for (int k = 0; k < PER_THREAD; k++) {
            float4 o = op[j * SLAB_STRIDE4 + k * NTHREADS];
            float4 t = tp[j * SLAB_STRIDE4 + k * NTHREADS];
            float d0 = o.x - t.x;
            float d1 = o.y - t.y;
            float d2 = o.z - t.z;
            float d3 = o.w - t.w;
            a0 = fmaf(d0, d0, a0);
            a1 = fmaf(d1, d1, a1);
            a2 = fmaf(d2, d2, a2);
            a3 = fmaf(d3, d3, a3);
        }
    }
    float acc = (a0 + a1) + (a2 + a3);

    // warp shuffle reduction (deterministic within-block tree)
    #pragma unroll
    for (int ofs = 16; ofs > 0; ofs >>= 1)
        acc += __shfl_down_sync(0xFFFFFFFFu, acc, ofs);

    __shared__ float swarp[NTHREADS / 32];
    const int lane = threadIdx.x & 31;
    const int wid  = threadIdx.x >> 5;
    if (lane == 0) swarp[wid] = acc;
    __syncthreads();

    if (threadIdx.x == 0) {
        float blk = 0.0f;
        #pragma unroll
        for (int w = 0; w < NTHREADS / 32; w++) blk += swarp[w];

        // Fire-and-forget: returnless reds, CTA retires immediately.
        asm volatile("red.add.relaxed.gpu.f32 [%0], %1;"
                     :: "l"(&g_accum), "f"(blk) : "memory");
        asm volatile("red.add.release.gpu.u32 [%0], %1;"
                     :: "l"(&g_count), "r"(1u) : "memory");

        // Spinner finalizes once all CTAs have arrived.
        if (blockIdx.x == NBLOCKS - 1) {
            unsigned int c;
            do {
                __nanosleep(200);
                asm volatile("ld.acquire.gpu.u32 %0, [%1];"
                             : "=r"(c) : "l"(&g_count));
            } while (c < (unsigned int)NBLOCKS);

            float total;
            asm volatile("ld.acquire.gpu.f32 %0, [%1];"
                         : "=f"(total) : "l"(&g_accum));
            const double scale = 1.0 / (524288.0 * 8.0);  // mean(C,H,Wd), /half_win
            result[0] = (float)((double)total * scale);

            // re-arm for next graph replay
            asm volatile("st.relaxed.gpu.f32 [%0], %1;"
                         :: "l"(&g_accum), "f"(0.0f) : "memory");
            asm volatile("st.relaxed.gpu.u32 [%0], %1;"
                         :: "l"(&g_count), "r"(0u) : "memory");
        }
    }
}

extern "C" void kernel_launch(void* const* d_in, const int* in_sizes, int n_in,
                              void* d_out, int out_size)
{
    const float4* out4 = (const float4*)d_in[0];
    const float4* tgt4 = (const float4*)d_in[1];
    float* o = (float*)d_out;

    cont_loss_fused_kernel<<<NBLOCKS, NTHREADS>>>(out4, tgt4, o);
}